// round 16
// baseline (speedup 1.0000x reference)
#include <cuda_runtime.h>
#include <math.h>

#define DD 128
#define VOL (DD*DD*DD)
#define NSL 16
#define NPIX (NSL*DD*DD)
#define CG_ITER 10

#define SC_RR   0
#define SC_PAP  16
#define SC_DUMP 31

#define TPB 128            // 16x8 pixel tile per block
#define PCELLS 125         // 5x5x5 private footprint
#define HEAVY_SMEM (PCELLS * TPB * 4)   // 64000 B -> 3 CTAs/SM

__device__ float g_x[VOL];
__device__ float g_r[VOL];
__device__ float g_p[VOL];
__device__ float g_Ap[VOL];
__device__ float g_b[VOL];
__device__ float g_scal[32];

__global__ void k_nop() {}

// ---------------- block reduction (sum) ----------------
__device__ __forceinline__ float block_sum(float v) {
    __shared__ float sh[8];
    int lane = threadIdx.x & 31, wid = threadIdx.x >> 5;
#pragma unroll
    for (int o = 16; o > 0; o >>= 1) v += __shfl_down_sync(0xffffffffu, v, o);
    if (lane == 0) sh[wid] = v;
    __syncthreads();
    if (wid == 0) {
        v = (lane < (blockDim.x >> 5)) ? sh[lane] : 0.f;
#pragma unroll
        for (int o = 4; o > 0; o >>= 1) v += __shfl_down_sync(0xffffffffu, v, o);
    }
    return v;
}

// ---------------- small vector kernels ----------------
__global__ void k_init(float4* __restrict__ b4, float4* __restrict__ ap4) {
    int i = blockIdx.x * blockDim.x + threadIdx.x;
    float4 z = make_float4(0.f, 0.f, 0.f, 0.f);
    if (i < VOL / 4) { b4[i] = z; ap4[i] = z; }
    if (i < 32) g_scal[i] = 0.f;
}

__global__ void k_rp0(float4* __restrict__ r4, float4* __restrict__ p4,
                      const float4* __restrict__ b4, float4* __restrict__ ap4) {
    int i = blockIdx.x * blockDim.x + threadIdx.x;
    float s = 0.f;
    if (i < VOL / 4) {
        float4 b = b4[i], a = ap4[i];
        float4 v = make_float4(b.x - a.x, b.y - a.y, b.z - a.z, b.w - a.w);
        r4[i] = v; p4[i] = v;
        ap4[i] = make_float4(0.f, 0.f, 0.f, 0.f);
        s = v.x * v.x + v.y * v.y + v.z * v.z + v.w * v.w;
    }
    s = block_sum(s);
    if (threadIdx.x == 0) atomicAdd(&g_scal[SC_RR + 0], s);
}

__global__ void k_xr(const float4* __restrict__ xin4, float4* __restrict__ xout4,
                     float4* __restrict__ r4, const float4* __restrict__ p4,
                     const float4* __restrict__ ap4, int it) {
    int i = blockIdx.x * blockDim.x + threadIdx.x;
    float s = 0.f;
    if (i < VOL / 4) {
        float a = g_scal[SC_RR + it] / g_scal[SC_PAP + it];
        float4 x = xin4[i], p = p4[i], ap = ap4[i], r = r4[i];
        x.x = fmaf(a, p.x, x.x); x.y = fmaf(a, p.y, x.y);
        x.z = fmaf(a, p.z, x.z); x.w = fmaf(a, p.w, x.w);
        r.x = fmaf(-a, ap.x, r.x); r.y = fmaf(-a, ap.y, r.y);
        r.z = fmaf(-a, ap.z, r.z); r.w = fmaf(-a, ap.w, r.w);
        xout4[i] = x; r4[i] = r;
        s = r.x * r.x + r.y * r.y + r.z * r.z + r.w * r.w;
    }
    s = block_sum(s);
    if (threadIdx.x == 0) atomicAdd(&g_scal[SC_RR + it + 1], s);
}

__global__ void k_updp(float4* __restrict__ p4, const float4* __restrict__ r4,
                       float4* __restrict__ ap4, int it) {
    int i = blockIdx.x * blockDim.x + threadIdx.x;
    if (i < VOL / 4) {
        float b = g_scal[SC_RR + it + 1] / g_scal[SC_RR + it];
        float4 p = p4[i], r = r4[i];
        p.x = fmaf(b, p.x, r.x); p.y = fmaf(b, p.y, r.y);
        p.z = fmaf(b, p.z, r.z); p.w = fmaf(b, p.w, r.w);
        p4[i] = p;
        ap4[i] = make_float4(0.f, 0.f, 0.f, 0.f);
    }
}

__global__ void k_relu(float4* __restrict__ o4, const float4* __restrict__ x4) {
    int i = blockIdx.x * blockDim.x + threadIdx.x;
    if (i < VOL / 4) {
        float4 x = x4[i];
        o4[i] = make_float4(fmaxf(x.x, 0.f), fmaxf(x.y, 0.f),
                            fmaxf(x.z, 0.f), fmaxf(x.w, 0.f));
    }
}

// ---------------- safe (boundary) helpers ----------------
__device__ __forceinline__ float tri_gather_safe(const float* __restrict__ vol,
                                                 float x, float y, float z) {
    float x0f = floorf(x), y0f = floorf(y), z0f = floorf(z);
    float fx = x - x0f, fy = y - y0f, fz = z - z0f;
    int x0 = (int)x0f, y0 = (int)y0f, z0 = (int)z0f;
    float v = 0.f;
#pragma unroll
    for (int dz = 0; dz < 2; dz++) {
        int zi = z0 + dz;
        if (zi < 0 || zi >= DD) continue;
        float wz = dz ? fz : 1.f - fz;
#pragma unroll
        for (int dy = 0; dy < 2; dy++) {
            int yi = y0 + dy;
            if (yi < 0 || yi >= DD) continue;
            float wzy = wz * (dy ? fy : 1.f - fy);
            int base = (zi << 14) + (yi << 7);
#pragma unroll
            for (int dx = 0; dx < 2; dx++) {
                int xi = x0 + dx;
                if (xi < 0 || xi >= DD) continue;
                v = fmaf(wzy * (dx ? fx : 1.f - fx), __ldg(vol + base + xi), v);
            }
        }
    }
    return v;
}

__device__ __forceinline__ void tri_scatter_safe(float* __restrict__ vol,
                                                 float x, float y, float z, float wv) {
    float x0f = floorf(x), y0f = floorf(y), z0f = floorf(z);
    float fx = x - x0f, fy = y - y0f, fz = z - z0f;
    int x0 = (int)x0f, y0 = (int)y0f, z0 = (int)z0f;
#pragma unroll
    for (int dz = 0; dz < 2; dz++) {
        int zi = z0 + dz;
        if (zi < 0 || zi >= DD) continue;
        float wz = (dz ? fz : 1.f - fz) * wv;
#pragma unroll
        for (int dy = 0; dy < 2; dy++) {
            int yi = y0 + dy;
            if (yi < 0 || yi >= DD) continue;
            float wzy = wz * (dy ? fy : 1.f - fy);
            int base = (zi << 14) + (yi << 7);
#pragma unroll
            for (int dx = 0; dx < 2; dx++) {
                int xi = x0 + dx;
                if (xi < 0 || xi >= DD) continue;
                atomicAdd(vol + base + xi, wzy * (dx ? fx : 1.f - fx));
            }
        }
    }
}

// ---------------- fused interior tap: gather + psf-weighted priv scatter ----------------
// Computes the 8 trilinear corner weights ONCE (pre-scaled by psf), uses them
// for both the gather dot-product (into acc) and the scale-invariant private
// tile accumulation (flush multiplies by acc later).
__device__ __forceinline__ void tap_fused(const float* __restrict__ vol,
                                          float* __restrict__ priv,
                                          int ox, int oy, int oz,
                                          float x, float y, float z,
                                          float psf, float& acc) {
    float x0f = floorf(x), y0f = floorf(y), z0f = floorf(z);
    float fx = x - x0f, fy = y - y0f, fz = z - z0f;
    int x0 = (int)x0f, y0 = (int)y0f, z0 = (int)z0f;
    int gi = (z0 << 14) + (y0 << 7) + x0;
    const float* p = vol + gi;
    float v000 = __ldg(p),         v001 = __ldg(p + 1);
    float v010 = __ldg(p + 128),   v011 = __ldg(p + 129);
    float v100 = __ldg(p + 16384), v101 = __ldg(p + 16385);
    float v110 = __ldg(p + 16512), v111 = __ldg(p + 16513);
    float wz1 = fz * psf, wz0 = psf - wz1;
    float w01 = fy * wz0, w00 = wz0 - w01;
    float w11 = fy * wz1, w10 = wz1 - w11;
    float t00 = fx * w00, s00 = w00 - t00;
    float t01 = fx * w01, s01 = w01 - t01;
    float t10 = fx * w10, s10 = w10 - t10;
    float t11 = fx * w11, s11 = w11 - t11;
    float tv = s00 * v000;
    tv = fmaf(t00, v001, tv); tv = fmaf(s01, v010, tv); tv = fmaf(t01, v011, tv);
    tv = fmaf(s10, v100, tv); tv = fmaf(t10, v101, tv);
    tv = fmaf(s11, v110, tv); tv = fmaf(t11, v111, tv);
    acc += tv;
    int c = (((z0 - oz) * 5 + (y0 - oy)) * 5 + (x0 - ox));
    priv[c * TPB]        += s00; priv[(c + 1) * TPB]  += t00;
    priv[(c + 5) * TPB]  += s01; priv[(c + 6) * TPB]  += t01;
    priv[(c + 25) * TPB] += s10; priv[(c + 26) * TPB] += t10;
    priv[(c + 30) * TPB] += s11; priv[(c + 31) * TPB] += t11;
}

// priv-only scatter (for k_At: value folded into wv)
__device__ __forceinline__ void tri_scatter_priv(float* __restrict__ priv,
                                                 int ox, int oy, int oz,
                                                 float x, float y, float z, float wv) {
    float x0f = floorf(x), y0f = floorf(y), z0f = floorf(z);
    float fx = x - x0f, fy = y - y0f, fz = z - z0f;
    int c = (((int)z0f - oz) * 5 + ((int)y0f - oy)) * 5 + ((int)x0f - ox);
    float wz1 = fz * wv, wz0 = wv - wz1;
    float w01 = fy * wz0, w00 = wz0 - w01;
    float w11 = fy * wz1, w10 = wz1 - w11;
    float t;
    t = fx * w00; priv[c * TPB]        += w00 - t; priv[(c + 1) * TPB]  += t;
    t = fx * w01; priv[(c + 5) * TPB]  += w01 - t; priv[(c + 6) * TPB]  += t;
    t = fx * w10; priv[(c + 25) * TPB] += w10 - t; priv[(c + 26) * TPB] += t;
    t = fx * w11; priv[(c + 30) * TPB] += w11 - t; priv[(c + 31) * TPB] += t;
}

// ---------------- geometry ----------------
struct Geo {
    float qx, qy, qz;
    float rx, ry, rz;
    int status;  // 0 reject, 1 interior fast, 2 boundary/fallback safe
};

__device__ __forceinline__ Geo pixel_geo(const float* sT, int w, int h) {
    Geo g;
    float u = (w - 63.5f) * 1.5f;
    float v = (h - 63.5f) * 1.5f;
    g.qx = sT[0] * u + sT[1] * v + sT[3]  + 63.5f;
    g.qy = sT[4] * u + sT[5] * v + sT[7]  + 63.5f;
    g.qz = sT[8] * u + sT[9] * v + sT[11] + 63.5f;
    g.rx = fabsf(sT[0]) + fabsf(sT[1]) + fabsf(sT[2]);
    g.ry = fabsf(sT[4]) + fabsf(sT[5]) + fabsf(sT[6]);
    g.rz = fabsf(sT[8]) + fabsf(sT[9]) + fabsf(sT[10]);
    bool rej = (g.qx + g.rx < -1.f) | (g.qx - g.rx >= 128.f) |
               (g.qy + g.ry < -1.f) | (g.qy - g.ry >= 128.f) |
               (g.qz + g.rz < -1.f) | (g.qz - g.rz >= 128.f);
    bool inter = (g.qx - g.rx >= 0.f) & (g.qx + g.rx < 127.f) &
                 (g.qy - g.ry >= 0.f) & (g.qy + g.ry < 127.f) &
                 (g.qz - g.rz >= 0.f) & (g.qz + g.rz < 127.f) &
                 (g.rx < 1.49f) & (g.ry < 1.49f) & (g.rz < 1.49f);
    g.status = rej ? 0 : (inter ? 1 : 2);
    return g;
}

__device__ __forceinline__ void zero_priv(float* __restrict__ priv) {
#pragma unroll
    for (int c = 0; c < PCELLS; c++) priv[c * TPB] = 0.f;
}

// flush with scale factor; fully unrolled, compile-time addressing, no bounds
// check (interior nonzero cells are in-bounds by construction)
__device__ __forceinline__ void flush_priv_scaled(const float* __restrict__ priv,
                                                  float* __restrict__ dst,
                                                  int ox, int oy, int oz, float scale) {
    int gb = (oz << 14) + (oy << 7) + ox;
#pragma unroll
    for (int cz = 0; cz < 5; cz++) {
#pragma unroll
        for (int cy = 0; cy < 5; cy++) {
#pragma unroll
            for (int cx = 0; cx < 5; cx++) {
                float v = priv[((cz * 5 + cy) * 5 + cx) * TPB];
                if (v != 0.f)
                    atomicAdd(dst + gb + (cz << 14) + (cy << 7) + cx, v * scale);
            }
        }
    }
}

// ---------------- fused AtA (single-pass gather+scatter) ----------------
__global__ void __launch_bounds__(TPB)
k_AtA(const float* __restrict__ th, const float* __restrict__ src,
      const float* __restrict__ psf, float* __restrict__ dst,
      float* __restrict__ pap) {
    extern __shared__ float scr[];
    __shared__ float sp[27];
    __shared__ float sT[12];
    int tid = threadIdx.x;
    int b = blockIdx.x;
    int n = b >> 7;                      // 128 blocks per slice
    if (tid < 27) sp[tid] = psf[tid];
    if (tid < 12) sT[tid] = th[n * 12 + tid];
    __syncthreads();
    int tile = b & 127;                  // 8 x-tiles * 16 y-tiles of 16x8 px
    int w = ((tile & 7) << 4) + (tid & 15);
    int h = ((tile >> 3) << 3) + (tid >> 4);

    float r00 = sT[0], r01 = sT[1], r02 = sT[2];
    float r10 = sT[4], r11 = sT[5], r12 = sT[6];
    float r20 = sT[8], r21 = sT[9], r22 = sT[10];
    Geo g = pixel_geo(sT, w, h);

    float acc = 0.f;
    float* priv = scr + tid;
    int ox = 0, oy = 0, oz = 0;

    if (g.status == 1) {
        zero_priv(priv);
        ox = (int)floorf(g.qx - g.rx);
        oy = (int)floorf(g.qy - g.ry);
        oz = (int)floorf(g.qz - g.rz);
        int k = 0;
#pragma unroll
        for (int iz = -1; iz <= 1; iz++) {
            float zx = g.qx + iz * r02, zy = g.qy + iz * r12, zz = g.qz + iz * r22;
#pragma unroll
            for (int iy = -1; iy <= 1; iy++) {
                float yx = zx + iy * r01, yy = zy + iy * r11, yz = zz + iy * r21;
#pragma unroll
                for (int ix = -1; ix <= 1; ix++, k++)
                    tap_fused(src, priv, ox, oy, oz,
                              yx + ix * r00, yy + ix * r10, yz + ix * r20,
                              sp[k], acc);
            }
        }
    } else if (g.status == 2) {
        int k = 0;
#pragma unroll
        for (int iz = -1; iz <= 1; iz++) {
            float zx = g.qx + iz * r02, zy = g.qy + iz * r12, zz = g.qz + iz * r22;
#pragma unroll
            for (int iy = -1; iy <= 1; iy++) {
                float yx = zx + iy * r01, yy = zy + iy * r11, yz = zz + iy * r21;
#pragma unroll
                for (int ix = -1; ix <= 1; ix++, k++)
                    acc = fmaf(sp[k], tri_gather_safe(src, yx + ix * r00,
                                                      yy + ix * r10, yz + ix * r20), acc);
            }
        }
    }

    float s = block_sum(acc * acc);
    if (tid == 0) atomicAdd(pap, s);

    if (acc == 0.f) return;
    if (g.status == 1) {
        flush_priv_scaled(priv, dst, ox, oy, oz, acc);
    } else if (g.status == 2) {
        int k = 0;
        for (int iz = -1; iz <= 1; iz++) {
            float zx = g.qx + iz * r02, zy = g.qy + iz * r12, zz = g.qz + iz * r22;
            for (int iy = -1; iy <= 1; iy++) {
                float yx = zx + iy * r01, yy = zy + iy * r11, yz = zz + iy * r21;
                for (int ix = -1; ix <= 1; ix++, k++)
                    tri_scatter_safe(dst, yx + ix * r00, yy + ix * r10,
                                     yz + ix * r20, acc * sp[k]);
            }
        }
    }
}

// ---------------- standalone At (b = At slices) ----------------
__global__ void __launch_bounds__(TPB)
k_At(const float* __restrict__ th, const float* __restrict__ sl,
     const float* __restrict__ psf, float* __restrict__ dst) {
    extern __shared__ float scr[];
    __shared__ float sp[27];
    __shared__ float sT[12];
    int tid = threadIdx.x;
    int b = blockIdx.x;
    int n = b >> 7;
    if (tid < 27) sp[tid] = psf[tid];
    if (tid < 12) sT[tid] = th[n * 12 + tid];
    __syncthreads();
    int tile = b & 127;
    int w = ((tile & 7) << 4) + (tid & 15);
    int h = ((tile >> 3) << 3) + (tid >> 4);

    float r00 = sT[0], r01 = sT[1], r02 = sT[2];
    float r10 = sT[4], r11 = sT[5], r12 = sT[6];
    float r20 = sT[8], r21 = sT[9], r22 = sT[10];
    Geo g = pixel_geo(sT, w, h);
    if (g.status == 0) return;
    float s = __ldg(sl + (n << 14) + (h << 7) + w);
    if (s == 0.f) return;
    if (g.status == 2) {
        int k = 0;
        for (int iz = -1; iz <= 1; iz++) {
            float zx = g.qx + iz * r02, zy = g.qy + iz * r12, zz = g.qz + iz * r22;
            for (int iy = -1; iy <= 1; iy++) {
                float yx = zx + iy * r01, yy = zy + iy * r11, yz = zz + iy * r21;
                for (int ix = -1; ix <= 1; ix++, k++)
                    tri_scatter_safe(dst, yx + ix * r00, yy + ix * r10,
                                     yz + ix * r20, s * sp[k]);
            }
        }
        return;
    }
    float* priv = scr + tid;
    zero_priv(priv);
    int ox = (int)floorf(g.qx - g.rx);
    int oy = (int)floorf(g.qy - g.ry);
    int oz = (int)floorf(g.qz - g.rz);
    int k = 0;
#pragma unroll
    for (int iz = -1; iz <= 1; iz++) {
        float zx = g.qx + iz * r02, zy = g.qy + iz * r12, zz = g.qz + iz * r22;
#pragma unroll
        for (int iy = -1; iy <= 1; iy++) {
            float yx = zx + iy * r01, yy = zy + iy * r11, yz = zz + iy * r21;
#pragma unroll
            for (int ix = -1; ix <= 1; ix++, k++)
                tri_scatter_priv(priv, ox, oy, oz, yx + ix * r00,
                                 yy + ix * r10, yz + ix * r20, sp[k]);
        }
    }
    flush_priv_scaled(priv, dst, ox, oy, oz, s);
}

// ---------------- host driver ----------------
extern "C" void kernel_launch(void* const* d_in, const int* in_sizes, int n_in,
                              void* d_out, int out_size) {
    const float *theta = nullptr, *slices = nullptr, *vol0 = nullptr, *psf = nullptr;
    for (int i = 0; i < n_in; i++) {
        switch (in_sizes[i]) {
            case 192:   theta  = (const float*)d_in[i]; break;
            case NPIX:  slices = (const float*)d_in[i]; break;
            case VOL:   vol0   = (const float*)d_in[i]; break;
            case 27:    psf    = (const float*)d_in[i]; break;
        }
    }

    float *px, *pr, *pp, *pap, *pb, *pscal;
    cudaGetSymbolAddress((void**)&px,    g_x);
    cudaGetSymbolAddress((void**)&pr,    g_r);
    cudaGetSymbolAddress((void**)&pp,    g_p);
    cudaGetSymbolAddress((void**)&pap,   g_Ap);
    cudaGetSymbolAddress((void**)&pb,    g_b);
    cudaGetSymbolAddress((void**)&pscal, g_scal);

    cudaFuncSetAttribute(k_AtA, cudaFuncAttributeMaxDynamicSharedMemorySize, HEAVY_SMEM);
    cudaFuncSetAttribute(k_At,  cudaFuncAttributeMaxDynamicSharedMemorySize, HEAVY_SMEM);

    const int V4B = (VOL / 4) / 256;   // 2048
    const int PB  = NPIX / TPB;        // 2048 pixel blocks (16x8 tiles)

    // launch #1: no-op so ncu (-s 5 -c 1) lands on the first in-loop k_AtA
    k_nop<<<1, 32>>>();
    k_init<<<V4B, 256>>>((float4*)pb, (float4*)pap);
    k_At<<<PB, TPB, HEAVY_SMEM>>>(theta, slices, psf, pb);
    k_AtA<<<PB, TPB, HEAVY_SMEM>>>(theta, vol0, psf, pap, pscal + SC_DUMP);
    k_rp0<<<V4B, 256>>>((float4*)pr, (float4*)pp, (float4*)pb, (float4*)pap);

    for (int it = 0; it < CG_ITER; it++) {
        k_AtA<<<PB, TPB, HEAVY_SMEM>>>(theta, pp, psf, pap, pscal + SC_PAP + it);
        const float* xin = (it == 0) ? vol0 : px;
        k_xr<<<V4B, 256>>>((const float4*)xin, (float4*)px, (float4*)pr,
                           (const float4*)pp, (const float4*)pap, it);
        k_updp<<<V4B, 256>>>((float4*)pp, (const float4*)pr, (float4*)pap, it);
    }

    k_relu<<<V4B, 256>>>((float4*)d_out, (const float4*)px);
    (void)out_size;
}